// round 1
// baseline (speedup 1.0000x reference)
#include <cuda_runtime.h>
#include <cuda_bf16.h>
#include <math.h>

// Problem constants
#define B_   128
#define S_   256
#define D_   1024
#define DH_  64
#define K_   8
#define L_   2
#define NROWS 18          // 16 gathered rows + vmax + vavg
#define MTOT (B_*2*NROWS) // 4608
#define NTOT 256          // q(64)|k(64)|v(64)|mi(64)

// -------- scratch (no allocations allowed) --------
__device__ float g_X[(size_t)MTOT * D_];   // gathered rows + pooled vectors, [row][1024]
__device__ float g_Y[(size_t)MTOT * NTOT]; // projection outputs, [row][256]

// =====================================================================
// Kernel 1: gather token rows per (b,s); fuse column-wise max/mean
// grid = B*2 blocks, 256 threads; thread t owns float4 column t.
// =====================================================================
__global__ void gather_kernel(const float* __restrict__ token,
                              const int* __restrict__ kw_idx)
{
    int bs = blockIdx.x;
    int b = bs >> 1, s = bs & 1;
    __shared__ int idx[K_];
    if (threadIdx.x < K_)
        idx[threadIdx.x] = kw_idx[(b * 2 + (1 - s)) * K_ + threadIdx.x];
    __syncthreads();

    int t = threadIdx.x; // float4 column 0..255
    float* Xrow = g_X + (size_t)bs * NROWS * D_;

    float4 mx = make_float4(-3.4e38f, -3.4e38f, -3.4e38f, -3.4e38f);
    float4 sm = make_float4(0.f, 0.f, 0.f, 0.f);

    #pragma unroll
    for (int r = 0; r < 16; r++) {
        int l = r >> 3, k = r & 7;
        const float4* src = reinterpret_cast<const float4*>(
            token + ((((size_t)b * 2 + s) * L_ + l) * S_ + idx[k]) * D_);
        float4 v = src[t];
        reinterpret_cast<float4*>(Xrow + (size_t)r * D_)[t] = v;
        mx.x = fmaxf(mx.x, v.x); mx.y = fmaxf(mx.y, v.y);
        mx.z = fmaxf(mx.z, v.z); mx.w = fmaxf(mx.w, v.w);
        sm.x += v.x; sm.y += v.y; sm.z += v.z; sm.w += v.w;
    }
    reinterpret_cast<float4*>(Xrow + (size_t)16 * D_)[t] = mx;
    sm.x *= (1.f/16.f); sm.y *= (1.f/16.f); sm.z *= (1.f/16.f); sm.w *= (1.f/16.f);
    reinterpret_cast<float4*>(Xrow + (size_t)17 * D_)[t] = sm;
}

// =====================================================================
// Kernel 2: SGEMM  g_Y[M,256] = g_X[M,1024] @ W^T
// 64x64 tile, BK=16, register prefetch. blockIdx.y selects weight matrix.
// =====================================================================
__global__ void __launch_bounds__(256, 4)
gemm_kernel(const float* __restrict__ wq, const float* __restrict__ wk,
            const float* __restrict__ wv, const float* __restrict__ wmi)
{
    const float* W = (blockIdx.y == 0) ? wq :
                     (blockIdx.y == 1) ? wk :
                     (blockIdx.y == 2) ? wv : wmi;

    __shared__ __align__(16) float As[16][68];
    __shared__ __align__(16) float Bs[16][68];

    int tid = threadIdx.x;
    int m0  = blockIdx.x * 64;
    int lr  = tid >> 2;          // row within tile for loading (0..63)
    int kc  = (tid & 3) * 4;     // k offset (float4)

    const float* Ag = g_X + (size_t)(m0 + lr) * D_ + kc;
    const float* Bg = W   + (size_t)lr * D_ + kc;

    int r0 = (tid >> 4) * 4;     // output rows
    int c0 = (tid & 15) * 4;     // output cols

    float acc[4][4];
    #pragma unroll
    for (int i = 0; i < 4; i++)
        #pragma unroll
        for (int j = 0; j < 4; j++) acc[i][j] = 0.f;

    float4 a = *reinterpret_cast<const float4*>(Ag);
    float4 bv = *reinterpret_cast<const float4*>(Bg);

    for (int kk = 0; kk < 64; kk++) {
        As[kc+0][lr] = a.x; As[kc+1][lr] = a.y; As[kc+2][lr] = a.z; As[kc+3][lr] = a.w;
        Bs[kc+0][lr] = bv.x; Bs[kc+1][lr] = bv.y; Bs[kc+2][lr] = bv.z; Bs[kc+3][lr] = bv.w;
        __syncthreads();

        if (kk < 63) {
            a  = *reinterpret_cast<const float4*>(Ag + (kk + 1) * 16);
            bv = *reinterpret_cast<const float4*>(Bg + (kk + 1) * 16);
        }

        #pragma unroll
        for (int j = 0; j < 16; j++) {
            float4 av = *reinterpret_cast<const float4*>(&As[j][r0]);
            float4 bb = *reinterpret_cast<const float4*>(&Bs[j][c0]);
            acc[0][0] += av.x * bb.x; acc[0][1] += av.x * bb.y;
            acc[0][2] += av.x * bb.z; acc[0][3] += av.x * bb.w;
            acc[1][0] += av.y * bb.x; acc[1][1] += av.y * bb.y;
            acc[1][2] += av.y * bb.z; acc[1][3] += av.y * bb.w;
            acc[2][0] += av.z * bb.x; acc[2][1] += av.z * bb.y;
            acc[2][2] += av.z * bb.z; acc[2][3] += av.z * bb.w;
            acc[3][0] += av.w * bb.x; acc[3][1] += av.w * bb.y;
            acc[3][2] += av.w * bb.z; acc[3][3] += av.w * bb.w;
        }
        __syncthreads();
    }

    int n0 = blockIdx.y * 64;
    #pragma unroll
    for (int i = 0; i < 4; i++) {
        float4 o = make_float4(acc[i][0], acc[i][1], acc[i][2], acc[i][3]);
        *reinterpret_cast<float4*>(g_Y + (size_t)(m0 + r0 + i) * NTOT + n0 + c0) = o;
    }
}

// =====================================================================
// Kernel 3: per-b heads. grid = B blocks, 128 threads.
// =====================================================================
__device__ __forceinline__ float gelu_f(float x) {
    return 0.5f * x * (1.0f + erff(x * 0.70710678118654752440f));
}

__global__ void head_kernel(const float* __restrict__ q_b, const float* __restrict__ k_b,
                            const float* __restrict__ v_b, const float* __restrict__ mi_b,
                            const float* __restrict__ inter_w, const float* __restrict__ inter_b,
                            const float* __restrict__ fc0_w, const float* __restrict__ fc0_b,
                            const float* __restrict__ fc1_w, const float* __restrict__ fc1_b,
                            float* __restrict__ out)
{
    __shared__ float q0[1024], k0[1024], v0[1024];
    __shared__ float q1[1024], k1[1024], v1[1024];
    __shared__ float att[512];       // [which][n][m]
    __shared__ float e1s[1024], e2s[1024];
    __shared__ float sv[4][64];      // s1_max, s1_avg, s2_max, s2_avg
    __shared__ float aV[256];        // inter outputs
    __shared__ float feat[516];
    __shared__ float h1[64];

    int b = blockIdx.x;
    int tid = threadIdx.x;
    const float* Y0 = g_Y + (size_t)(b * 2 + 0) * NROWS * NTOT;
    const float* Y1 = g_Y + (size_t)(b * 2 + 1) * NROWS * NTOT;

    for (int t = tid; t < 1024; t += 128) {
        int n = t >> 6, h = t & 63;
        q0[t] = Y0[n * NTOT +       h] + q_b[h];
        k0[t] = Y0[n * NTOT +  64 + h] + k_b[h];
        v0[t] = Y0[n * NTOT + 128 + h] + v_b[h];
        q1[t] = Y1[n * NTOT +       h] + q_b[h];
        k1[t] = Y1[n * NTOT +  64 + h] + k_b[h];
        v1[t] = Y1[n * NTOT + 128 + h] + v_b[h];
    }
    if (tid < 64) {
        int h = tid;
        sv[0][h] = Y0[16 * NTOT + 192 + h] + mi_b[h];
        sv[1][h] = Y0[17 * NTOT + 192 + h] + mi_b[h];
        sv[2][h] = Y1[16 * NTOT + 192 + h] + mi_b[h];
        sv[3][h] = Y1[17 * NTOT + 192 + h] + mi_b[h];
    }
    __syncthreads();

    // att1 = q0 @ k1^T / 8 ; att2 = q1 @ k0^T / 8
    for (int e = tid; e < 512; e += 128) {
        int which = e >> 8, n = (e >> 4) & 15, m = e & 15;
        const float* qq = which ? q1 : q0;
        const float* kk = which ? k0 : k1;
        float s = 0.f;
        #pragma unroll
        for (int h = 0; h < 64; h++) s += qq[n * 64 + h] * kk[m * 64 + h];
        att[e] = s * 0.125f;
    }
    __syncthreads();

    // e1 = att1 @ v1 ; e2 = att2 @ v0
    for (int e = tid; e < 2048; e += 128) {
        int which = e >> 10, n = (e >> 6) & 15, h = e & 63;
        const float* vv = which ? v0 : v1;
        float s = 0.f;
        #pragma unroll
        for (int m = 0; m < 16; m++) s += att[which * 256 + n * 16 + m] * vv[m * 64 + h];
        (which ? e2s : e1s)[n * 64 + h] = s;
    }
    __syncthreads();

    // att_feat: [e1max, e1mean, e2max, e2mean]  -> feat[0..255]
    if (tid < 128) {
        int which = tid >> 6, hh = tid & 63;
        const float* E = which ? e2s : e1s;
        float mx = -3.4e38f, sm = 0.f;
        #pragma unroll
        for (int n = 0; n < 16; n++) { float v = E[n * 64 + hh]; mx = fmaxf(mx, v); sm += v; }
        feat[which * 128 + hh]      = mx;
        feat[which * 128 + 64 + hh] = sm * (1.f / 16.f);
    }

    // inter_i applied to s1_max (i=0,1) / s1_avg (i=2,3)
    for (int e = tid; e < 256; e += 128) {
        int i = e >> 6, j = e & 63;
        const float* src = sv[i >> 1];
        float s = inter_b[i * 64 + j];
        const float* wrow = inter_w + ((size_t)i * 64 + j) * 64;
        #pragma unroll
        for (int h = 0; h < 64; h++) s += wrow[h] * src[h];
        aV[i * 64 + j] = s;
    }
    __syncthreads();

    // cosines
    if (tid < 4) {
        int i = tid;
        const float* av = aV + i * 64;
        const float* bvv = sv[2 + (i & 1)];
        float dot = 0.f, na = 0.f, nb = 0.f;
        #pragma unroll
        for (int h = 0; h < 64; h++) {
            dot += av[h] * bvv[h];
            na  += av[h] * av[h];
            nb  += bvv[h] * bvv[h];
        }
        na = fmaxf(sqrtf(na), 1e-8f);
        nb = fmaxf(sqrtf(nb), 1e-8f);
        feat[256 + i] = dot / (na * nb);
    }
    // s vectors into feature
    for (int t = tid; t < 256; t += 128)
        feat[260 + t] = sv[t >> 6][t & 63];
    __syncthreads();

    // fc0 + gelu
    if (tid < 64) {
        float s = fc0_b[tid];
        const float* wrow = fc0_w + (size_t)tid * 516;
        for (int i = 0; i < 516; i++) s += feat[i] * wrow[i];
        h1[tid] = gelu_f(s);
    }
    __syncthreads();

    // fc1 + gelu + softmax
    if (tid == 0) {
        float l0 = fc1_b[0], l1 = fc1_b[1];
        #pragma unroll
        for (int j = 0; j < 64; j++) { l0 += h1[j] * fc1_w[j]; l1 += h1[j] * fc1_w[64 + j]; }
        l0 = gelu_f(l0); l1 = gelu_f(l1);
        float m = fmaxf(l0, l1);
        float ea = expf(l0 - m), eb = expf(l1 - m);
        float inv = 1.f / (ea + eb);
        out[b * 2 + 0] = ea * inv;
        out[b * 2 + 1] = eb * inv;
    }
}

// =====================================================================
extern "C" void kernel_launch(void* const* d_in, const int* in_sizes, int n_in,
                              void* d_out, int out_size)
{
    const float* token   = (const float*)d_in[0];
    const int*   kw_idx  = (const int*)  d_in[1];
    const float* q_w     = (const float*)d_in[2];
    const float* q_b     = (const float*)d_in[3];
    const float* k_w     = (const float*)d_in[4];
    const float* k_b     = (const float*)d_in[5];
    const float* v_w     = (const float*)d_in[6];
    const float* v_b     = (const float*)d_in[7];
    const float* mi_w    = (const float*)d_in[8];
    const float* mi_b    = (const float*)d_in[9];
    const float* inter_w = (const float*)d_in[10];
    const float* inter_b = (const float*)d_in[11];
    const float* fc0_w   = (const float*)d_in[12];
    const float* fc0_b   = (const float*)d_in[13];
    const float* fc1_w   = (const float*)d_in[14];
    const float* fc1_b   = (const float*)d_in[15];
    float* out = (float*)d_out;

    gather_kernel<<<B_ * 2, 256>>>(token, kw_idx);
    gemm_kernel<<<dim3(MTOT / 64, 4), 256>>>(q_w, k_w, v_w, mi_w);
    head_kernel<<<B_, 128>>>(q_b, k_b, v_b, mi_b, inter_w, inter_b,
                             fc0_w, fc0_b, fc1_w, fc1_b, out);
}

// round 2
// speedup vs baseline: 1.3057x; 1.3057x over previous
#include <cuda_runtime.h>
#include <cuda_bf16.h>
#include <math.h>
#include <stdint.h>

// Problem constants
#define B_   128
#define S_   256
#define D_   1024
#define DH_  64
#define K_   8
#define L_   2
#define NROWS 18          // 16 gathered rows + vmax + vavg
#define MTOT (B_*2*NROWS) // 4608
#define NTOT 256          // q(64)|k(64)|v(64)|mi(64)

// -------- scratch (no allocations allowed) --------
__device__ float g_X[(size_t)MTOT * D_];   // gathered rows + pooled vectors
__device__ float g_Y[(size_t)MTOT * NTOT]; // projection outputs

// =====================================================================
// Kernel 1: gather token rows per (b,s); fuse column-wise max/mean
// =====================================================================
__global__ void gather_kernel(const float* __restrict__ token,
                              const int* __restrict__ kw_idx)
{
    int bs = blockIdx.x;
    int b = bs >> 1, s = bs & 1;
    __shared__ int idx[K_];
    if (threadIdx.x < K_)
        idx[threadIdx.x] = kw_idx[(b * 2 + (1 - s)) * K_ + threadIdx.x];
    __syncthreads();

    int t = threadIdx.x; // float4 column 0..255
    float* Xrow = g_X + (size_t)bs * NROWS * D_;

    float4 mx = make_float4(-3.4e38f, -3.4e38f, -3.4e38f, -3.4e38f);
    float4 sm = make_float4(0.f, 0.f, 0.f, 0.f);

    #pragma unroll
    for (int r = 0; r < 16; r++) {
        int l = r >> 3, k = r & 7;
        const float4* src = reinterpret_cast<const float4*>(
            token + ((((size_t)b * 2 + s) * L_ + l) * S_ + idx[k]) * D_);
        float4 v = src[t];
        reinterpret_cast<float4*>(Xrow + (size_t)r * D_)[t] = v;
        mx.x = fmaxf(mx.x, v.x); mx.y = fmaxf(mx.y, v.y);
        mx.z = fmaxf(mx.z, v.z); mx.w = fmaxf(mx.w, v.w);
        sm.x += v.x; sm.y += v.y; sm.z += v.z; sm.w += v.w;
    }
    reinterpret_cast<float4*>(Xrow + (size_t)16 * D_)[t] = mx;
    sm.x *= (1.f/16.f); sm.y *= (1.f/16.f); sm.z *= (1.f/16.f); sm.w *= (1.f/16.f);
    reinterpret_cast<float4*>(Xrow + (size_t)17 * D_)[t] = sm;
}

// =====================================================================
// Kernel 2: tf32 tensor-core GEMM  g_Y[M,256] = g_X[M,1024] @ W^T
// 64x64x32 block tile, 8 warps (2x4), warp tile 32x16 via m16n8k8 mma.
// =====================================================================
__device__ __forceinline__ uint32_t f2tf32(float f) {
    uint32_t u;
    asm("cvt.rna.tf32.f32 %0, %1;" : "=r"(u) : "f"(f));
    return u;
}

#define SMS 36  // padded smem row stride (conflict-free fragment LDS)

__global__ void __launch_bounds__(256, 2)
gemm_tc_kernel(const float* __restrict__ wq, const float* __restrict__ wk,
               const float* __restrict__ wv, const float* __restrict__ wmi)
{
    const float* W = (blockIdx.y == 0) ? wq :
                     (blockIdx.y == 1) ? wk :
                     (blockIdx.y == 2) ? wv : wmi;

    __shared__ __align__(16) uint32_t As[64 * SMS];
    __shared__ __align__(16) uint32_t Bs[64 * SMS];

    const int tid  = threadIdx.x;
    const int lane = tid & 31;
    const int warp = tid >> 5;
    const int wm   = warp >> 2;     // 0..1
    const int wn   = warp & 3;      // 0..3
    const int m0   = blockIdx.x * 64;

    // global loader mapping: 4 threads per row, 2 float4 each (k and k+16)
    const int lrow = tid >> 2;      // 0..63
    const int lq   = (tid & 3) * 4; // 0,4,8,12

    const float* Ag = g_X + (size_t)(m0 + lrow) * D_ + lq;
    const float* Bg = W   + (size_t)lrow * D_ + lq;

    float c[2][2][4];
    #pragma unroll
    for (int i = 0; i < 2; i++)
        #pragma unroll
        for (int j = 0; j < 2; j++)
            #pragma unroll
            for (int r = 0; r < 4; r++) c[i][j][r] = 0.f;

    float4 ra0 = *reinterpret_cast<const float4*>(Ag);
    float4 ra1 = *reinterpret_cast<const float4*>(Ag + 16);
    float4 rb0 = *reinterpret_cast<const float4*>(Bg);
    float4 rb1 = *reinterpret_cast<const float4*>(Bg + 16);

    const int g = lane >> 2;        // groupID 0..7
    const int tg = lane & 3;        // thread-in-group 0..3

    for (int kt = 0; kt < 32; kt++) {
        // stage tiles (convert to tf32)
        {
            uint32_t* a = As + lrow * SMS + lq;
            a[0] = f2tf32(ra0.x); a[1] = f2tf32(ra0.y);
            a[2] = f2tf32(ra0.z); a[3] = f2tf32(ra0.w);
            a[16] = f2tf32(ra1.x); a[17] = f2tf32(ra1.y);
            a[18] = f2tf32(ra1.z); a[19] = f2tf32(ra1.w);
            uint32_t* bp = Bs + lrow * SMS + lq;
            bp[0] = f2tf32(rb0.x); bp[1] = f2tf32(rb0.y);
            bp[2] = f2tf32(rb0.z); bp[3] = f2tf32(rb0.w);
            bp[16] = f2tf32(rb1.x); bp[17] = f2tf32(rb1.y);
            bp[18] = f2tf32(rb1.z); bp[19] = f2tf32(rb1.w);
        }
        __syncthreads();

        if (kt < 31) {
            const float* An = Ag + (kt + 1) * 32;
            const float* Bn = Bg + (kt + 1) * 32;
            ra0 = *reinterpret_cast<const float4*>(An);
            ra1 = *reinterpret_cast<const float4*>(An + 16);
            rb0 = *reinterpret_cast<const float4*>(Bn);
            rb1 = *reinterpret_cast<const float4*>(Bn + 16);
        }

        #pragma unroll
        for (int step = 0; step < 4; step++) {
            const int kb = step * 8;
            uint32_t a[2][4], bf[2][2];
            #pragma unroll
            for (int mt = 0; mt < 2; mt++) {
                const uint32_t* base = As + (wm * 32 + mt * 16 + g) * SMS + kb + tg;
                a[mt][0] = base[0];
                a[mt][1] = base[8 * SMS];
                a[mt][2] = base[4];
                a[mt][3] = base[8 * SMS + 4];
            }
            #pragma unroll
            for (int nt = 0; nt < 2; nt++) {
                const uint32_t* base = Bs + (wn * 16 + nt * 8 + g) * SMS + kb + tg;
                bf[nt][0] = base[0];
                bf[nt][1] = base[4];
            }
            #pragma unroll
            for (int mt = 0; mt < 2; mt++)
                #pragma unroll
                for (int nt = 0; nt < 2; nt++) {
                    asm volatile(
                        "mma.sync.aligned.m16n8k8.row.col.f32.tf32.tf32.f32 "
                        "{%0,%1,%2,%3}, {%4,%5,%6,%7}, {%8,%9}, {%0,%1,%2,%3};"
                        : "+f"(c[mt][nt][0]), "+f"(c[mt][nt][1]),
                          "+f"(c[mt][nt][2]), "+f"(c[mt][nt][3])
                        : "r"(a[mt][0]), "r"(a[mt][1]), "r"(a[mt][2]), "r"(a[mt][3]),
                          "r"(bf[nt][0]), "r"(bf[nt][1]));
                }
        }
        __syncthreads();
    }

    // epilogue
    const int n0 = blockIdx.y * 64;
    #pragma unroll
    for (int mt = 0; mt < 2; mt++) {
        const int rA = m0 + wm * 32 + mt * 16 + g;
        #pragma unroll
        for (int nt = 0; nt < 2; nt++) {
            const int col = n0 + wn * 16 + nt * 8 + 2 * tg;
            *reinterpret_cast<float2*>(g_Y + (size_t)rA * NTOT + col) =
                make_float2(c[mt][nt][0], c[mt][nt][1]);
            *reinterpret_cast<float2*>(g_Y + (size_t)(rA + 8) * NTOT + col) =
                make_float2(c[mt][nt][2], c[mt][nt][3]);
        }
    }
}

// =====================================================================
// Kernel 3: per-b heads. grid = B blocks, 128 threads.
// =====================================================================
__device__ __forceinline__ float gelu_f(float x) {
    return 0.5f * x * (1.0f + erff(x * 0.70710678118654752440f));
}

__global__ void head_kernel(const float* __restrict__ q_b, const float* __restrict__ k_b,
                            const float* __restrict__ v_b, const float* __restrict__ mi_b,
                            const float* __restrict__ inter_w, const float* __restrict__ inter_b,
                            const float* __restrict__ fc0_w, const float* __restrict__ fc0_b,
                            const float* __restrict__ fc1_w, const float* __restrict__ fc1_b,
                            float* __restrict__ out)
{
    __shared__ float q0[1024], k0[1024], v0[1024];
    __shared__ float q1[1024], k1[1024], v1[1024];
    __shared__ float att[512];
    __shared__ float e1s[1024], e2s[1024];
    __shared__ float sv[4][64];
    __shared__ float aV[256];
    __shared__ float feat[516];
    __shared__ float h1[64];

    int b = blockIdx.x;
    int tid = threadIdx.x;
    const float* Y0 = g_Y + (size_t)(b * 2 + 0) * NROWS * NTOT;
    const float* Y1 = g_Y + (size_t)(b * 2 + 1) * NROWS * NTOT;

    for (int t = tid; t < 1024; t += 128) {
        int n = t >> 6, h = t & 63;
        q0[t] = Y0[n * NTOT +       h] + q_b[h];
        k0[t] = Y0[n * NTOT +  64 + h] + k_b[h];
        v0[t] = Y0[n * NTOT + 128 + h] + v_b[h];
        q1[t] = Y1[n * NTOT +       h] + q_b[h];
        k1[t] = Y1[n * NTOT +  64 + h] + k_b[h];
        v1[t] = Y1[n * NTOT + 128 + h] + v_b[h];
    }
    if (tid < 64) {
        int h = tid;
        sv[0][h] = Y0[16 * NTOT + 192 + h] + mi_b[h];
        sv[1][h] = Y0[17 * NTOT + 192 + h] + mi_b[h];
        sv[2][h] = Y1[16 * NTOT + 192 + h] + mi_b[h];
        sv[3][h] = Y1[17 * NTOT + 192 + h] + mi_b[h];
    }
    __syncthreads();

    for (int e = tid; e < 512; e += 128) {
        int which = e >> 8, n = (e >> 4) & 15, m = e & 15;
        const float* qq = which ? q1 : q0;
        const float* kk = which ? k0 : k1;
        float s = 0.f;
        #pragma unroll
        for (int h = 0; h < 64; h++) s += qq[n * 64 + h] * kk[m * 64 + h];
        att[e] = s * 0.125f;
    }
    __syncthreads();

    for (int e = tid; e < 2048; e += 128) {
        int which = e >> 10, n = (e >> 6) & 15, h = e & 63;
        const float* vv = which ? v0 : v1;
        float s = 0.f;
        #pragma unroll
        for (int m = 0; m < 16; m++) s += att[which * 256 + n * 16 + m] * vv[m * 64 + h];
        (which ? e2s : e1s)[n * 64 + h] = s;
    }
    __syncthreads();

    if (tid < 128) {
        int which = tid >> 6, hh = tid & 63;
        const float* E = which ? e2s : e1s;
        float mx = -3.4e38f, sm = 0.f;
        #pragma unroll
        for (int n = 0; n < 16; n++) { float v = E[n * 64 + hh]; mx = fmaxf(mx, v); sm += v; }
        feat[which * 128 + hh]      = mx;
        feat[which * 128 + 64 + hh] = sm * (1.f / 16.f);
    }

    for (int e = tid; e < 256; e += 128) {
        int i = e >> 6, j = e & 63;
        const float* src = sv[i >> 1];
        float s = inter_b[i * 64 + j];
        const float* wrow = inter_w + ((size_t)i * 64 + j) * 64;
        #pragma unroll
        for (int h = 0; h < 64; h++) s += wrow[h] * src[h];
        aV[i * 64 + j] = s;
    }
    __syncthreads();

    if (tid < 4) {
        int i = tid;
        const float* av = aV + i * 64;
        const float* bvv = sv[2 + (i & 1)];
        float dot = 0.f, na = 0.f, nb = 0.f;
        #pragma unroll
        for (int h = 0; h < 64; h++) {
            dot += av[h] * bvv[h];
            na  += av[h] * av[h];
            nb  += bvv[h] * bvv[h];
        }
        na = fmaxf(sqrtf(na), 1e-8f);
        nb = fmaxf(sqrtf(nb), 1e-8f);
        feat[256 + i] = dot / (na * nb);
    }
    for (int t = tid; t < 256; t += 128)
        feat[260 + t] = sv[t >> 6][t & 63];
    __syncthreads();

    // fc0 + gelu, 2 threads per output with shfl combine
    {
        int j = tid >> 1, half = tid & 1;
        const float* wrow = fc0_w + (size_t)j * 516 + half * 258;
        const float* fr = feat + half * 258;
        float s = 0.f;
        #pragma unroll 4
        for (int i = 0; i < 258; i++) s += fr[i] * wrow[i];
        s += __shfl_xor_sync(0xffffffff, s, 1);
        if (half == 0) h1[j] = gelu_f(fc0_b[j] + s);
    }
    __syncthreads();

    if (tid == 0) {
        float l0 = fc1_b[0], l1 = fc1_b[1];
        #pragma unroll
        for (int j = 0; j < 64; j++) { l0 += h1[j] * fc1_w[j]; l1 += h1[j] * fc1_w[64 + j]; }
        l0 = gelu_f(l0); l1 = gelu_f(l1);
        float m = fmaxf(l0, l1);
        float ea = expf(l0 - m), eb = expf(l1 - m);
        float inv = 1.f / (ea + eb);
        out[b * 2 + 0] = ea * inv;
        out[b * 2 + 1] = eb * inv;
    }
}

// =====================================================================
extern "C" void kernel_launch(void* const* d_in, const int* in_sizes, int n_in,
                              void* d_out, int out_size)
{
    const float* token   = (const float*)d_in[0];
    const int*   kw_idx  = (const int*)  d_in[1];
    const float* q_w     = (const float*)d_in[2];
    const float* q_b     = (const float*)d_in[3];
    const float* k_w     = (const float*)d_in[4];
    const float* k_b     = (const float*)d_in[5];
    const float* v_w     = (const float*)d_in[6];
    const float* v_b     = (const float*)d_in[7];
    const float* mi_w    = (const float*)d_in[8];
    const float* mi_b    = (const float*)d_in[9];
    const float* inter_w = (const float*)d_in[10];
    const float* inter_b = (const float*)d_in[11];
    const float* fc0_w   = (const float*)d_in[12];
    const float* fc0_b   = (const float*)d_in[13];
    const float* fc1_w   = (const float*)d_in[14];
    const float* fc1_b   = (const float*)d_in[15];
    float* out = (float*)d_out;

    gather_kernel<<<B_ * 2, 256>>>(token, kw_idx);
    gemm_tc_kernel<<<dim3(MTOT / 64, 4), 256>>>(q_w, k_w, v_w, mi_w);
    head_kernel<<<B_, 128>>>(q_b, k_b, v_b, mi_b, inter_w, inter_b,
                             fc0_w, fc0_b, fc1_w, fc1_b, out);
}

// round 3
// speedup vs baseline: 1.7863x; 1.3681x over previous
#include <cuda_runtime.h>
#include <cuda_bf16.h>
#include <math.h>
#include <stdint.h>

// Problem constants
#define B_   128
#define S_   256
#define D_   1024
#define DH_  64
#define K_   8
#define L_   2
#define NROWS 18          // 16 gathered rows + vmax + vavg
#define MTOT (B_*2*NROWS) // 4608
#define NTOT 256          // q(64)|k(64)|v(64)|mi(64)

// -------- scratch (no allocations allowed) --------
__device__ uint32_t g_Xt[(size_t)MTOT * D_];   // gathered rows + pooled, tf32 bits
__device__ uint32_t g_Wt[(size_t)NTOT * D_];   // packed weights q|k|v|mi, tf32 bits
__device__ float    g_Y [(size_t)MTOT * NTOT]; // projection outputs (f32)

__device__ __forceinline__ uint32_t f2tf32(float f) {
    uint32_t u;
    asm("cvt.rna.tf32.f32 %0, %1;" : "=r"(u) : "f"(f));
    return u;
}
__device__ __forceinline__ uint4 cvt4(float4 v) {
    uint4 u;
    u.x = f2tf32(v.x); u.y = f2tf32(v.y); u.z = f2tf32(v.z); u.w = f2tf32(v.w);
    return u;
}

// =====================================================================
// Kernel 1: gather (blocks 0..255) + weight pack (blocks 256..319)
// =====================================================================
__global__ void __launch_bounds__(1024)
gather_pack_kernel(const float* __restrict__ token,
                   const int* __restrict__ kw_idx,
                   const float* __restrict__ wq, const float* __restrict__ wk,
                   const float* __restrict__ wv, const float* __restrict__ wmi)
{
    if (blockIdx.x >= 256) {
        // pack 4x [64][1024] weights into g_Wt tf32
        int e0 = (blockIdx.x - 256) * 4096 + threadIdx.x;
        #pragma unroll
        for (int i = 0; i < 4; i++) {
            int e = e0 + i * 1024;
            int wsel = e >> 16;
            int off = e & 65535;
            const float* W = (wsel == 0) ? wq : (wsel == 1) ? wk :
                             (wsel == 2) ? wv : wmi;
            g_Wt[e] = f2tf32(W[off]);
        }
        return;
    }

    __shared__ int idx[K_];
    __shared__ float4 pmax[4][256];
    __shared__ float4 psum[4][256];

    int bs = blockIdx.x;
    int b = bs >> 1, s = bs & 1;
    if (threadIdx.x < K_)
        idx[threadIdx.x] = kw_idx[(b * 2 + (1 - s)) * K_ + threadIdx.x];
    __syncthreads();

    int col = threadIdx.x & 255;   // float4 column
    int rp  = threadIdx.x >> 8;    // row group 0..3
    uint32_t* Xrow = g_Xt + (size_t)bs * NROWS * D_;

    float4 mx = make_float4(-3.4e38f, -3.4e38f, -3.4e38f, -3.4e38f);
    float4 sm = make_float4(0.f, 0.f, 0.f, 0.f);

    #pragma unroll
    for (int j = 0; j < 4; j++) {
        int r = rp * 4 + j;
        int l = r >> 3, k = r & 7;
        float4 v = reinterpret_cast<const float4*>(
            token + ((((size_t)b * 2 + s) * L_ + l) * S_ + idx[k]) * D_)[col];
        reinterpret_cast<uint4*>(Xrow + (size_t)r * D_)[col] = cvt4(v);
        mx.x = fmaxf(mx.x, v.x); mx.y = fmaxf(mx.y, v.y);
        mx.z = fmaxf(mx.z, v.z); mx.w = fmaxf(mx.w, v.w);
        sm.x += v.x; sm.y += v.y; sm.z += v.z; sm.w += v.w;
    }
    pmax[rp][col] = mx;
    psum[rp][col] = sm;
    __syncthreads();

    if (threadIdx.x < 256) {
        float4 m0 = pmax[0][col], m1 = pmax[1][col], m2 = pmax[2][col], m3 = pmax[3][col];
        float4 s0 = psum[0][col], s1 = psum[1][col], s2 = psum[2][col], s3 = psum[3][col];
        float4 M, S;
        M.x = fmaxf(fmaxf(m0.x, m1.x), fmaxf(m2.x, m3.x));
        M.y = fmaxf(fmaxf(m0.y, m1.y), fmaxf(m2.y, m3.y));
        M.z = fmaxf(fmaxf(m0.z, m1.z), fmaxf(m2.z, m3.z));
        M.w = fmaxf(fmaxf(m0.w, m1.w), fmaxf(m2.w, m3.w));
        S.x = (s0.x + s1.x + s2.x + s3.x) * (1.f/16.f);
        S.y = (s0.y + s1.y + s2.y + s3.y) * (1.f/16.f);
        S.z = (s0.z + s1.z + s2.z + s3.z) * (1.f/16.f);
        S.w = (s0.w + s1.w + s2.w + s3.w) * (1.f/16.f);
        reinterpret_cast<uint4*>(Xrow + (size_t)16 * D_)[col] = cvt4(M);
        reinterpret_cast<uint4*>(Xrow + (size_t)17 * D_)[col] = cvt4(S);
    }
}

// =====================================================================
// Kernel 2: tf32 tensor GEMM, 64x64x64 tiles, 3-stage cp.async pipeline
// =====================================================================
#define SROW 68                    // padded row stride (u32) — conflict-free frags
#define STG_U32 (64 * SROW)        // 4352 u32 per matrix per stage
#define STG_TOT (2 * STG_U32)      // A + B per stage
#define GEMM_SMEM (3 * STG_TOT * 4)  // 104448 bytes

extern __shared__ uint32_t smem_g[];

__device__ __forceinline__ void cp_async16(uint32_t* dst, const uint32_t* src) {
    uint32_t d = (uint32_t)__cvta_generic_to_shared(dst);
    asm volatile("cp.async.cg.shared.global [%0], [%1], 16;" :: "r"(d), "l"(src));
}

__global__ void __launch_bounds__(256, 2)
gemm_tc_kernel()
{
    uint32_t* smb = smem_g;
    const int tid  = threadIdx.x;
    const int lane = tid & 31;
    const int warp = tid >> 5;
    const int wm   = warp >> 2;     // 0..1
    const int wn   = warp & 3;      // 0..3
    const int m0   = blockIdx.x * 64;
    const int n0   = blockIdx.y * 64;
    const int g    = lane >> 2;     // groupID 0..7
    const int tg   = lane & 3;      // thread-in-group

    const uint32_t* gA = g_Xt + (size_t)m0 * D_;
    const uint32_t* gB = g_Wt + (size_t)n0 * D_;

    float c[2][2][4];
    #pragma unroll
    for (int i = 0; i < 2; i++)
        #pragma unroll
        for (int j = 0; j < 2; j++)
            #pragma unroll
            for (int r = 0; r < 4; r++) c[i][j][r] = 0.f;

    // loader: 4 chunks of 16B each for A and B per stage
    #define ISSUE(kt, stg) { \
        uint32_t* dA = smb + (stg) * STG_TOT; \
        uint32_t* dB = dA + STG_U32; \
        _Pragma("unroll") \
        for (int i = 0; i < 4; i++) { \
            int cch = tid + i * 256; \
            int row = cch >> 4; \
            int kc  = (cch & 15) * 4; \
            cp_async16(dA + row * SROW + kc, gA + (size_t)row * D_ + (kt) * 64 + kc); \
            cp_async16(dB + row * SROW + kc, gB + (size_t)row * D_ + (kt) * 64 + kc); \
        } \
    }

    ISSUE(0, 0);
    asm volatile("cp.async.commit_group;");
    ISSUE(1, 1);
    asm volatile("cp.async.commit_group;");

    for (int kt = 0; kt < 16; kt++) {
        asm volatile("cp.async.wait_group 1;");
        __syncthreads();

        const uint32_t* As = smb + (kt % 3) * STG_TOT;
        const uint32_t* Bs = As + STG_U32;

        #pragma unroll
        for (int step = 0; step < 8; step++) {
            const int kb = step * 8;
            uint32_t a[2][4], bf[2][2];
            #pragma unroll
            for (int mt = 0; mt < 2; mt++) {
                const uint32_t* base = As + (wm * 32 + mt * 16 + g) * SROW + kb + tg;
                a[mt][0] = base[0];
                a[mt][1] = base[8 * SROW];
                a[mt][2] = base[4];
                a[mt][3] = base[8 * SROW + 4];
            }
            #pragma unroll
            for (int nt = 0; nt < 2; nt++) {
                const uint32_t* base = Bs + (wn * 16 + nt * 8 + g) * SROW + kb + tg;
                bf[nt][0] = base[0];
                bf[nt][1] = base[4];
            }
            #pragma unroll
            for (int mt = 0; mt < 2; mt++)
                #pragma unroll
                for (int nt = 0; nt < 2; nt++) {
                    asm volatile(
                        "mma.sync.aligned.m16n8k8.row.col.f32.tf32.tf32.f32 "
                        "{%0,%1,%2,%3}, {%4,%5,%6,%7}, {%8,%9}, {%0,%1,%2,%3};"
                        : "+f"(c[mt][nt][0]), "+f"(c[mt][nt][1]),
                          "+f"(c[mt][nt][2]), "+f"(c[mt][nt][3])
                        : "r"(a[mt][0]), "r"(a[mt][1]), "r"(a[mt][2]), "r"(a[mt][3]),
                          "r"(bf[nt][0]), "r"(bf[nt][1]));
                }
        }

        if (kt + 2 < 16) { ISSUE(kt + 2, (kt + 2) % 3); }
        asm volatile("cp.async.commit_group;");
    }

    // epilogue
    #pragma unroll
    for (int mt = 0; mt < 2; mt++) {
        const int rA = m0 + wm * 32 + mt * 16 + g;
        #pragma unroll
        for (int nt = 0; nt < 2; nt++) {
            const int col = n0 + wn * 16 + nt * 8 + 2 * tg;
            *reinterpret_cast<float2*>(g_Y + (size_t)rA * NTOT + col) =
                make_float2(c[mt][nt][0], c[mt][nt][1]);
            *reinterpret_cast<float2*>(g_Y + (size_t)(rA + 8) * NTOT + col) =
                make_float2(c[mt][nt][2], c[mt][nt][3]);
        }
    }
}

// =====================================================================
// Kernel 3: per-b heads. grid = B blocks, 256 threads.
// =====================================================================
__device__ __forceinline__ float gelu_f(float x) {
    return 0.5f * x * (1.0f + erff(x * 0.70710678118654752440f));
}

__global__ void __launch_bounds__(256)
head_kernel(const float* __restrict__ q_b, const float* __restrict__ k_b,
            const float* __restrict__ v_b, const float* __restrict__ mi_b,
            const float* __restrict__ inter_w, const float* __restrict__ inter_b,
            const float* __restrict__ fc0_w, const float* __restrict__ fc0_b,
            const float* __restrict__ fc1_w, const float* __restrict__ fc1_b,
            float* __restrict__ out)
{
    __shared__ float q0[1024], k0[1024], v0[1024];
    __shared__ float q1[1024], k1[1024], v1[1024];
    __shared__ float att[512];
    __shared__ float e1s[1024], e2s[1024];
    __shared__ float sv[4][64];
    __shared__ float aV[256];
    __shared__ float feat[516];
    __shared__ float h1[64];

    int b = blockIdx.x;
    int tid = threadIdx.x;
    const float* Y0 = g_Y + (size_t)(b * 2 + 0) * NROWS * NTOT;
    const float* Y1 = g_Y + (size_t)(b * 2 + 1) * NROWS * NTOT;

    for (int t = tid; t < 1024; t += 256) {
        int n = t >> 6, h = t & 63;
        q0[t] = Y0[n * NTOT +       h] + q_b[h];
        k0[t] = Y0[n * NTOT +  64 + h] + k_b[h];
        v0[t] = Y0[n * NTOT + 128 + h] + v_b[h];
        q1[t] = Y1[n * NTOT +       h] + q_b[h];
        k1[t] = Y1[n * NTOT +  64 + h] + k_b[h];
        v1[t] = Y1[n * NTOT + 128 + h] + v_b[h];
    }
    if (tid < 64) {
        int h = tid;
        sv[0][h] = Y0[16 * NTOT + 192 + h] + mi_b[h];
        sv[1][h] = Y0[17 * NTOT + 192 + h] + mi_b[h];
        sv[2][h] = Y1[16 * NTOT + 192 + h] + mi_b[h];
        sv[3][h] = Y1[17 * NTOT + 192 + h] + mi_b[h];
    }
    __syncthreads();

    for (int e = tid; e < 512; e += 256) {
        int which = e >> 8, n = (e >> 4) & 15, m = e & 15;
        const float* qq = which ? q1 : q0;
        const float* kk = which ? k0 : k1;
        float s = 0.f;
        #pragma unroll
        for (int h = 0; h < 64; h++) s += qq[n * 64 + h] * kk[m * 64 + h];
        att[e] = s * 0.125f;
    }
    __syncthreads();

    for (int e = tid; e < 2048; e += 256) {
        int which = e >> 10, n = (e >> 6) & 15, h = e & 63;
        const float* vv = which ? v0 : v1;
        float s = 0.f;
        #pragma unroll
        for (int m = 0; m < 16; m++) s += att[which * 256 + n * 16 + m] * vv[m * 64 + h];
        (which ? e2s : e1s)[n * 64 + h] = s;
    }
    __syncthreads();

    if (tid < 128) {
        int which = tid >> 6, hh = tid & 63;
        const float* E = which ? e2s : e1s;
        float mx = -3.4e38f, sm = 0.f;
        #pragma unroll
        for (int n = 0; n < 16; n++) { float v = E[n * 64 + hh]; mx = fmaxf(mx, v); sm += v; }
        feat[which * 128 + hh]      = mx;
        feat[which * 128 + 64 + hh] = sm * (1.f / 16.f);
    }

    {
        int i = tid >> 6, j = tid & 63;
        const float* src = sv[i >> 1];
        float s = inter_b[i * 64 + j];
        const float* wrow = inter_w + ((size_t)i * 64 + j) * 64;
        #pragma unroll
        for (int h = 0; h < 64; h++) s += wrow[h] * src[h];
        aV[i * 64 + j] = s;
    }
    __syncthreads();

    if (tid < 4) {
        int i = tid;
        const float* av = aV + i * 64;
        const float* bvv = sv[2 + (i & 1)];
        float dot = 0.f, na = 0.f, nb = 0.f;
        #pragma unroll
        for (int h = 0; h < 64; h++) {
            dot += av[h] * bvv[h];
            na  += av[h] * av[h];
            nb  += bvv[h] * bvv[h];
        }
        na = fmaxf(sqrtf(na), 1e-8f);
        nb = fmaxf(sqrtf(nb), 1e-8f);
        feat[256 + i] = dot / (na * nb);
    }
    feat[260 + tid] = sv[tid >> 6][tid & 63];
    __syncthreads();

    // fc0 + gelu, 4 threads per output with shfl combine
    {
        int j = tid >> 2, part = tid & 3;
        const float* wrow = fc0_w + (size_t)j * 516 + part * 129;
        const float* fr = feat + part * 129;
        float s = 0.f;
        #pragma unroll 4
        for (int i = 0; i < 129; i++) s += fr[i] * wrow[i];
        s += __shfl_xor_sync(0xffffffff, s, 1);
        s += __shfl_xor_sync(0xffffffff, s, 2);
        if (part == 0) h1[j] = gelu_f(fc0_b[j] + s);
    }
    __syncthreads();

    if (tid == 0) {
        float l0 = fc1_b[0], l1 = fc1_b[1];
        #pragma unroll
        for (int j = 0; j < 64; j++) { l0 += h1[j] * fc1_w[j]; l1 += h1[j] * fc1_w[64 + j]; }
        l0 = gelu_f(l0); l1 = gelu_f(l1);
        float m = fmaxf(l0, l1);
        float ea = expf(l0 - m), eb = expf(l1 - m);
        float inv = 1.f / (ea + eb);
        out[b * 2 + 0] = ea * inv;
        out[b * 2 + 1] = eb * inv;
    }
}

// =====================================================================
extern "C" void kernel_launch(void* const* d_in, const int* in_sizes, int n_in,
                              void* d_out, int out_size)
{
    const float* token   = (const float*)d_in[0];
    const int*   kw_idx  = (const int*)  d_in[1];
    const float* q_w     = (const float*)d_in[2];
    const float* q_b     = (const float*)d_in[3];
    const float* k_w     = (const float*)d_in[4];
    const float* k_b     = (const float*)d_in[5];
    const float* v_w     = (const float*)d_in[6];
    const float* v_b     = (const float*)d_in[7];
    const float* mi_w    = (const float*)d_in[8];
    const float* mi_b    = (const float*)d_in[9];
    const float* inter_w = (const float*)d_in[10];
    const float* inter_b = (const float*)d_in[11];
    const float* fc0_w   = (const float*)d_in[12];
    const float* fc0_b   = (const float*)d_in[13];
    const float* fc1_w   = (const float*)d_in[14];
    const float* fc1_b   = (const float*)d_in[15];
    float* out = (float*)d_out;

    cudaFuncSetAttribute(gemm_tc_kernel,
                         cudaFuncAttributeMaxDynamicSharedMemorySize, GEMM_SMEM);

    gather_pack_kernel<<<256 + 64, 1024>>>(token, kw_idx, q_w, k_w, v_w, mi_w);
    gemm_tc_kernel<<<dim3(MTOT / 64, 4), 256, GEMM_SMEM>>>();
    head_kernel<<<B_, 256>>>(q_b, k_b, v_b, mi_b, inter_w, inter_b,
                             fc0_w, fc0_b, fc1_w, fc1_b, out);
}

// round 4
// speedup vs baseline: 2.3500x; 1.3155x over previous
#include <cuda_runtime.h>
#include <cuda_bf16.h>
#include <math.h>
#include <stdint.h>

// Problem constants
#define B_   128
#define S_   256
#define D_   1024
#define DH_  64
#define K_   8
#define L_   2
#define NROWS 18          // 16 gathered rows + vmax + vavg
#define MTOT (B_*2*NROWS) // 4608
#define NTOT 256          // q(64)|k(64)|v(64)|mi(64)

// -------- scratch (no allocations allowed) --------
__device__ uint16_t g_Xb[(size_t)MTOT * D_];   // gathered rows + pooled, bf16
__device__ uint16_t g_Wb[(size_t)NTOT * D_];   // packed weights q|k|v|mi, bf16
__device__ float    g_Y [(size_t)MTOT * NTOT]; // projection outputs (f32)

__device__ __forceinline__ uint2 f4_to_bf4(float4 v) {
    __nv_bfloat162 lo = __floats2bfloat162_rn(v.x, v.y);
    __nv_bfloat162 hi = __floats2bfloat162_rn(v.z, v.w);
    uint2 r;
    r.x = *reinterpret_cast<uint32_t*>(&lo);
    r.y = *reinterpret_cast<uint32_t*>(&hi);
    return r;
}

// =====================================================================
// Kernel 1: gather (blocks 0..255) + weight pack (blocks 256..319)
// =====================================================================
__global__ void __launch_bounds__(1024)
gather_pack_kernel(const float* __restrict__ token,
                   const int* __restrict__ kw_idx,
                   const float* __restrict__ wq, const float* __restrict__ wk,
                   const float* __restrict__ wv, const float* __restrict__ wmi)
{
    if (blockIdx.x >= 256) {
        int e0 = (blockIdx.x - 256) * 4096 + threadIdx.x;
        #pragma unroll
        for (int i = 0; i < 4; i++) {
            int e = e0 + i * 1024;
            int wsel = e >> 16;
            int off = e & 65535;
            const float* W = (wsel == 0) ? wq : (wsel == 1) ? wk :
                             (wsel == 2) ? wv : wmi;
            g_Wb[e] = __bfloat16_as_ushort(__float2bfloat16_rn(W[off]));
        }
        return;
    }

    __shared__ int idx[K_];
    __shared__ float4 pmax[4][256];
    __shared__ float4 psum[4][256];

    int bs = blockIdx.x;
    int b = bs >> 1, s = bs & 1;
    if (threadIdx.x < K_)
        idx[threadIdx.x] = kw_idx[(b * 2 + (1 - s)) * K_ + threadIdx.x];
    __syncthreads();

    int col = threadIdx.x & 255;   // float4 column 0..255
    int rp  = threadIdx.x >> 8;    // row group 0..3
    uint16_t* Xrow = g_Xb + (size_t)bs * NROWS * D_;

    float4 mx = make_float4(-3.4e38f, -3.4e38f, -3.4e38f, -3.4e38f);
    float4 sm = make_float4(0.f, 0.f, 0.f, 0.f);

    #pragma unroll
    for (int j = 0; j < 4; j++) {
        int r = rp * 4 + j;
        int l = r >> 3, k = r & 7;
        float4 v = reinterpret_cast<const float4*>(
            token + ((((size_t)b * 2 + s) * L_ + l) * S_ + idx[k]) * D_)[col];
        reinterpret_cast<uint2*>(Xrow + (size_t)r * D_)[col] = f4_to_bf4(v);
        mx.x = fmaxf(mx.x, v.x); mx.y = fmaxf(mx.y, v.y);
        mx.z = fmaxf(mx.z, v.z); mx.w = fmaxf(mx.w, v.w);
        sm.x += v.x; sm.y += v.y; sm.z += v.z; sm.w += v.w;
    }
    pmax[rp][col] = mx;
    psum[rp][col] = sm;
    __syncthreads();

    if (threadIdx.x < 256) {
        float4 m0 = pmax[0][col], m1 = pmax[1][col], m2 = pmax[2][col], m3 = pmax[3][col];
        float4 s0 = psum[0][col], s1 = psum[1][col], s2 = psum[2][col], s3 = psum[3][col];
        float4 M, S;
        M.x = fmaxf(fmaxf(m0.x, m1.x), fmaxf(m2.x, m3.x));
        M.y = fmaxf(fmaxf(m0.y, m1.y), fmaxf(m2.y, m3.y));
        M.z = fmaxf(fmaxf(m0.z, m1.z), fmaxf(m2.z, m3.z));
        M.w = fmaxf(fmaxf(m0.w, m1.w), fmaxf(m2.w, m3.w));
        S.x = (s0.x + s1.x + s2.x + s3.x) * (1.f/16.f);
        S.y = (s0.y + s1.y + s2.y + s3.y) * (1.f/16.f);
        S.z = (s0.z + s1.z + s2.z + s3.z) * (1.f/16.f);
        S.w = (s0.w + s1.w + s2.w + s3.w) * (1.f/16.f);
        reinterpret_cast<uint2*>(Xrow + (size_t)16 * D_)[col] = f4_to_bf4(M);
        reinterpret_cast<uint2*>(Xrow + (size_t)17 * D_)[col] = f4_to_bf4(S);
    }
}

// =====================================================================
// Kernel 2: bf16 tensor GEMM  g_Y[M,256] = X @ W^T
// 64x64x64 tiles, 3-stage cp.async, XOR-swizzled smem, ldmatrix.x4,
// mma.m16n8k16.bf16.
// =====================================================================
#define STG_E 4096                 // 64x64 bf16 elems per matrix per stage
#define STG_TOT (2 * STG_E)        // A + B
#define GEMM_SMEM (3 * STG_TOT * 2)  // 49152 bytes

__device__ __forceinline__ void cp_async16(uint32_t dst_s, const uint16_t* src) {
    asm volatile("cp.async.cg.shared.global [%0], [%1], 16;" :: "r"(dst_s), "l"(src));
}

__global__ void __launch_bounds__(256, 2)
gemm_tc_kernel()
{
    extern __shared__ __align__(16) uint16_t smem_b[];
    const uint32_t smem_s = (uint32_t)__cvta_generic_to_shared(smem_b);

    const int tid  = threadIdx.x;
    const int lane = tid & 31;
    const int warp = tid >> 5;
    const int wm   = warp >> 2;     // 0..1
    const int wn   = warp & 3;      // 0..3
    const int m0   = blockIdx.x * 64;
    const int n0   = blockIdx.y * 64;

    const uint16_t* gA = g_Xb + (size_t)m0 * D_;
    const uint16_t* gB = g_Wb + (size_t)n0 * D_;

    float c[2][2][4];
    #pragma unroll
    for (int i = 0; i < 2; i++)
        #pragma unroll
        for (int j = 0; j < 2; j++)
            #pragma unroll
            for (int r = 0; r < 4; r++) c[i][j][r] = 0.f;

    // loader: 1024 16B-chunks per stage (512 A + 512 B); 4 per thread.
    #define ISSUE(kt, stg) { \
        uint32_t base = smem_s + (stg) * (STG_TOT * 2); \
        _Pragma("unroll") \
        for (int i = 0; i < 4; i++) { \
            int cc  = tid + i * 256; \
            int cm  = cc & 511; \
            int row = cm >> 3; \
            int ch  = cm & 7; \
            uint32_t dst = base + (i >= 2 ? STG_E * 2 : 0) \
                         + row * 128 + ((ch ^ (row & 7)) << 4); \
            const uint16_t* src = (i >= 2 ? gB : gA) \
                         + (size_t)row * D_ + (kt) * 64 + ch * 8; \
            cp_async16(dst, src); \
        } \
    }

    ISSUE(0, 0);
    asm volatile("cp.async.commit_group;");
    ISSUE(1, 1);
    asm volatile("cp.async.commit_group;");

    // per-lane ldmatrix geometry (constant across kt/step)
    const int j4   = lane >> 3;          // matrix index 0..3
    const int lr   = lane & 7;           // row within 8x8 matrix
    const int aRow = wm * 32 + (j4 & 1) * 8 + lr;   // mt=0 row
    const int aKj  = j4 >> 1;            // k-chunk bit for A
    const int aSw  = aRow & 7;
    const int bRow = wn * 16 + (j4 >> 1) * 8 + lr;
    const int bKj  = j4 & 1;
    const int bSw  = bRow & 7;
    const uint32_t aByte0 = aRow * 128;            // mt=0
    const uint32_t aByte1 = (aRow + 16) * 128;     // mt=1
    const uint32_t bByte  = bRow * 128;

    for (int kt = 0; kt < 16; kt++) {
        asm volatile("cp.async.wait_group 1;");
        __syncthreads();

        const uint32_t As = smem_s + (kt % 3) * (STG_TOT * 2);
        const uint32_t Bs = As + STG_E * 2;

        #pragma unroll
        for (int step = 0; step < 4; step++) {
            const int cA = (2 * step + aKj) ^ aSw;
            const int cB = (2 * step + bKj) ^ bSw;
            uint32_t a0[4], a1[4], bb[4];
            {
                uint32_t addr = As + aByte0 + (cA << 4);
                asm volatile("ldmatrix.sync.aligned.m8n8.x4.shared.b16 {%0,%1,%2,%3}, [%4];"
                             : "=r"(a0[0]), "=r"(a0[1]), "=r"(a0[2]), "=r"(a0[3]) : "r"(addr));
            }
            {
                uint32_t addr = As + aByte1 + (cA << 4);
                asm volatile("ldmatrix.sync.aligned.m8n8.x4.shared.b16 {%0,%1,%2,%3}, [%4];"
                             : "=r"(a1[0]), "=r"(a1[1]), "=r"(a1[2]), "=r"(a1[3]) : "r"(addr));
            }
            {
                uint32_t addr = Bs + bByte + (cB << 4);
                asm volatile("ldmatrix.sync.aligned.m8n8.x4.shared.b16 {%0,%1,%2,%3}, [%4];"
                             : "=r"(bb[0]), "=r"(bb[1]), "=r"(bb[2]), "=r"(bb[3]) : "r"(addr));
            }
            #pragma unroll
            for (int nt = 0; nt < 2; nt++) {
                asm volatile(
                    "mma.sync.aligned.m16n8k16.row.col.f32.bf16.bf16.f32 "
                    "{%0,%1,%2,%3}, {%4,%5,%6,%7}, {%8,%9}, {%0,%1,%2,%3};"
                    : "+f"(c[0][nt][0]), "+f"(c[0][nt][1]),
                      "+f"(c[0][nt][2]), "+f"(c[0][nt][3])
                    : "r"(a0[0]), "r"(a0[1]), "r"(a0[2]), "r"(a0[3]),
                      "r"(bb[nt*2]), "r"(bb[nt*2+1]));
                asm volatile(
                    "mma.sync.aligned.m16n8k16.row.col.f32.bf16.bf16.f32 "
                    "{%0,%1,%2,%3}, {%4,%5,%6,%7}, {%8,%9}, {%0,%1,%2,%3};"
                    : "+f"(c[1][nt][0]), "+f"(c[1][nt][1]),
                      "+f"(c[1][nt][2]), "+f"(c[1][nt][3])
                    : "r"(a1[0]), "r"(a1[1]), "r"(a1[2]), "r"(a1[3]),
                      "r"(bb[nt*2]), "r"(bb[nt*2+1]));
            }
        }

        if (kt + 2 < 16) { ISSUE(kt + 2, (kt + 2) % 3); }
        asm volatile("cp.async.commit_group;");
    }

    // epilogue: c0,c1 -> row g cols 2tg..; c2,c3 -> row g+8
    const int g  = lane >> 2;
    const int tg = lane & 3;
    #pragma unroll
    for (int mt = 0; mt < 2; mt++) {
        const int rA = m0 + wm * 32 + mt * 16 + g;
        #pragma unroll
        for (int nt = 0; nt < 2; nt++) {
            const int col = n0 + wn * 16 + nt * 8 + 2 * tg;
            *reinterpret_cast<float2*>(g_Y + (size_t)rA * NTOT + col) =
                make_float2(c[mt][nt][0], c[mt][nt][1]);
            *reinterpret_cast<float2*>(g_Y + (size_t)(rA + 8) * NTOT + col) =
                make_float2(c[mt][nt][2], c[mt][nt][3]);
        }
    }
}

// =====================================================================
// Kernel 3: per-b heads. grid = B blocks, 256 threads.
// =====================================================================
__device__ __forceinline__ float gelu_f(float x) {
    return 0.5f * x * (1.0f + erff(x * 0.70710678118654752440f));
}

__global__ void __launch_bounds__(256)
head_kernel(const float* __restrict__ q_b, const float* __restrict__ k_b,
            const float* __restrict__ v_b, const float* __restrict__ mi_b,
            const float* __restrict__ inter_w, const float* __restrict__ inter_b,
            const float* __restrict__ fc0_w, const float* __restrict__ fc0_b,
            const float* __restrict__ fc1_w, const float* __restrict__ fc1_b,
            float* __restrict__ out)
{
    __shared__ float q0[1024], k0[1024], v0[1024];
    __shared__ float q1[1024], k1[1024], v1[1024];
    __shared__ float att[512];
    __shared__ float e1s[1024], e2s[1024];
    __shared__ float sv[4][64];
    __shared__ float aV[256];
    __shared__ float feat[516];
    __shared__ float h1[64];

    int b = blockIdx.x;
    int tid = threadIdx.x;
    const float* Y0 = g_Y + (size_t)(b * 2 + 0) * NROWS * NTOT;
    const float* Y1 = g_Y + (size_t)(b * 2 + 1) * NROWS * NTOT;

    for (int t = tid; t < 1024; t += 256) {
        int n = t >> 6, h = t & 63;
        q0[t] = Y0[n * NTOT +       h] + q_b[h];
        k0[t] = Y0[n * NTOT +  64 + h] + k_b[h];
        v0[t] = Y0[n * NTOT + 128 + h] + v_b[h];
        q1[t] = Y1[n * NTOT +       h] + q_b[h];
        k1[t] = Y1[n * NTOT +  64 + h] + k_b[h];
        v1[t] = Y1[n * NTOT + 128 + h] + v_b[h];
    }
    if (tid < 64) {
        int h = tid;
        sv[0][h] = Y0[16 * NTOT + 192 + h] + mi_b[h];
        sv[1][h] = Y0[17 * NTOT + 192 + h] + mi_b[h];
        sv[2][h] = Y1[16 * NTOT + 192 + h] + mi_b[h];
        sv[3][h] = Y1[17 * NTOT + 192 + h] + mi_b[h];
    }
    __syncthreads();

    for (int e = tid; e < 512; e += 256) {
        int which = e >> 8, n = (e >> 4) & 15, m = e & 15;
        const float* qq = which ? q1 : q0;
        const float* kk = which ? k0 : k1;
        float s = 0.f;
        #pragma unroll
        for (int h = 0; h < 64; h++) s += qq[n * 64 + h] * kk[m * 64 + h];
        att[e] = s * 0.125f;
    }
    __syncthreads();

    for (int e = tid; e < 2048; e += 256) {
        int which = e >> 10, n = (e >> 6) & 15, h = e & 63;
        const float* vv = which ? v0 : v1;
        float s = 0.f;
        #pragma unroll
        for (int m = 0; m < 16; m++) s += att[which * 256 + n * 16 + m] * vv[m * 64 + h];
        (which ? e2s : e1s)[n * 64 + h] = s;
    }
    __syncthreads();

    if (tid < 128) {
        int which = tid >> 6, hh = tid & 63;
        const float* E = which ? e2s : e1s;
        float mx = -3.4e38f, sm = 0.f;
        #pragma unroll
        for (int n = 0; n < 16; n++) { float v = E[n * 64 + hh]; mx = fmaxf(mx, v); sm += v; }
        feat[which * 128 + hh]      = mx;
        feat[which * 128 + 64 + hh] = sm * (1.f / 16.f);
    }

    {
        int i = tid >> 6, j = tid & 63;
        const float* src = sv[i >> 1];
        float s = inter_b[i * 64 + j];
        const float* wrow = inter_w + ((size_t)i * 64 + j) * 64;
        #pragma unroll
        for (int h = 0; h < 64; h++) s += wrow[h] * src[h];
        aV[i * 64 + j] = s;
    }
    __syncthreads();

    if (tid < 4) {
        int i = tid;
        const float* av = aV + i * 64;
        const float* bvv = sv[2 + (i & 1)];
        float dot = 0.f, na = 0.f, nb = 0.f;
        #pragma unroll
        for (int h = 0; h < 64; h++) {
            dot += av[h] * bvv[h];
            na  += av[h] * av[h];
            nb  += bvv[h] * bvv[h];
        }
        na = fmaxf(sqrtf(na), 1e-8f);
        nb = fmaxf(sqrtf(nb), 1e-8f);
        feat[256 + i] = dot / (na * nb);
    }
    feat[260 + tid] = sv[tid >> 6][tid & 63];
    __syncthreads();

    {
        int j = tid >> 2, part = tid & 3;
        const float* wrow = fc0_w + (size_t)j * 516 + part * 129;
        const float* fr = feat + part * 129;
        float s = 0.f;
        #pragma unroll 4
        for (int i = 0; i < 129; i++) s += fr[i] * wrow[i];
        s += __shfl_xor_sync(0xffffffff, s, 1);
        s += __shfl_xor_sync(0xffffffff, s, 2);
        if (part == 0) h1[j] = gelu_f(fc0_b[j] + s);
    }
    __syncthreads();

    if (tid == 0) {
        float l0 = fc1_b[0], l1 = fc1_b[1];
        #pragma unroll
        for (int j = 0; j < 64; j++) { l0 += h1[j] * fc1_w[j]; l1 += h1[j] * fc1_w[64 + j]; }
        l0 = gelu_f(l0); l1 = gelu_f(l1);
        float m = fmaxf(l0, l1);
        float ea = expf(l0 - m), eb = expf(l1 - m);
        float inv = 1.f / (ea + eb);
        out[b * 2 + 0] = ea * inv;
        out[b * 2 + 1] = eb * inv;
    }
}

// =====================================================================
extern "C" void kernel_launch(void* const* d_in, const int* in_sizes, int n_in,
                              void* d_out, int out_size)
{
    const float* token   = (const float*)d_in[0];
    const int*   kw_idx  = (const int*)  d_in[1];
    const float* q_w     = (const float*)d_in[2];
    const float* q_b     = (const float*)d_in[3];
    const float* k_w     = (const float*)d_in[4];
    const float* k_b     = (const float*)d_in[5];
    const float* v_w     = (const float*)d_in[6];
    const float* v_b     = (const float*)d_in[7];
    const float* mi_w    = (const float*)d_in[8];
    const float* mi_b    = (const float*)d_in[9];
    const float* inter_w = (const float*)d_in[10];
    const float* inter_b = (const float*)d_in[11];
    const float* fc0_w   = (const float*)d_in[12];
    const float* fc0_b   = (const float*)d_in[13];
    const float* fc1_w   = (const float*)d_in[14];
    const float* fc1_b   = (const float*)d_in[15];
    float* out = (float*)d_out;

    cudaFuncSetAttribute(gemm_tc_kernel,
                         cudaFuncAttributeMaxDynamicSharedMemorySize, GEMM_SMEM);

    gather_pack_kernel<<<256 + 64, 1024>>>(token, kw_idx, q_w, k_w, v_w, mi_w);
    gemm_tc_kernel<<<dim3(MTOT / 64, 4), 256, GEMM_SMEM>>>();
    head_kernel<<<B_, 256>>>(q_b, k_b, v_b, mi_b, inter_w, inter_b,
                             fc0_w, fc0_b, fc1_w, fc1_b, out);
}

// round 5
// speedup vs baseline: 2.5822x; 1.0988x over previous
#include <cuda_runtime.h>
#include <cuda_bf16.h>
#include <math.h>
#include <stdint.h>

// Problem constants
#define B_   128
#define S_   256
#define D_   1024
#define DH_  64
#define K_   8
#define L_   2
#define NROWS 18          // 16 gathered rows + vmax + vavg
#define MTOT (B_*2*NROWS) // 4608
#define NTOT 256          // q(64)|k(64)|v(64)|mi(64)

// -------- scratch (no allocations allowed) --------
__device__ uint16_t g_Xb[(size_t)MTOT * D_];   // gathered rows + pooled, bf16
__device__ uint16_t g_Wb[(size_t)NTOT * D_];   // packed weights q|k|v|mi, bf16
__device__ float    g_Y [(size_t)MTOT * NTOT]; // projection outputs (f32)

__device__ __forceinline__ uint2 f4_to_bf4(float4 v) {
    __nv_bfloat162 lo = __floats2bfloat162_rn(v.x, v.y);
    __nv_bfloat162 hi = __floats2bfloat162_rn(v.z, v.w);
    uint2 r;
    r.x = *reinterpret_cast<uint32_t*>(&lo);
    r.y = *reinterpret_cast<uint32_t*>(&hi);
    return r;
}

// =====================================================================
// Kernel 1: gather (blocks 0..255, thread-per-column, no smem reduce)
//           + weight pack (blocks 256..319)
// =====================================================================
__global__ void __launch_bounds__(256)
gather_pack_kernel(const float* __restrict__ token,
                   const int* __restrict__ kw_idx,
                   const float* __restrict__ wq, const float* __restrict__ wk,
                   const float* __restrict__ wv, const float* __restrict__ wmi)
{
    int tid = threadIdx.x;
    if (blockIdx.x >= 256) {
        // pack 4x [64][1024] f32 weights into g_Wb bf16 (vectorized)
        int f4base = (blockIdx.x - 256) * 1024 + tid; // float4 index step 256
        #pragma unroll
        for (int i = 0; i < 4; i++) {
            int f4 = f4base + i * 256;        // 0..65535
            int wsel = f4 >> 14;              // 16384 float4 per matrix
            const float* W = (wsel == 0) ? wq : (wsel == 1) ? wk :
                             (wsel == 2) ? wv : wmi;
            float4 v = reinterpret_cast<const float4*>(W)[f4 & 16383];
            reinterpret_cast<uint2*>(g_Wb)[f4] = f4_to_bf4(v);
        }
        return;
    }

    __shared__ int idx[K_];
    int bs = blockIdx.x;
    int b = bs >> 1, s = bs & 1;
    if (tid < K_)
        idx[tid] = kw_idx[(b * 2 + (1 - s)) * K_ + tid];
    __syncthreads();

    const float* tbase = token + (((size_t)b * 2 + s) * L_) * S_ * D_;
    uint16_t* Xrow = g_Xb + (size_t)bs * NROWS * D_;

    float4 mx = make_float4(-3.4e38f, -3.4e38f, -3.4e38f, -3.4e38f);
    float4 sm = make_float4(0.f, 0.f, 0.f, 0.f);

    #pragma unroll
    for (int r = 0; r < 16; r++) {
        int l = r >> 3, k = r & 7;
        float4 v = reinterpret_cast<const float4*>(
            tbase + ((size_t)l * S_ + idx[k]) * D_)[tid];
        reinterpret_cast<uint2*>(Xrow + (size_t)r * D_)[tid] = f4_to_bf4(v);
        mx.x = fmaxf(mx.x, v.x); mx.y = fmaxf(mx.y, v.y);
        mx.z = fmaxf(mx.z, v.z); mx.w = fmaxf(mx.w, v.w);
        sm.x += v.x; sm.y += v.y; sm.z += v.z; sm.w += v.w;
    }
    reinterpret_cast<uint2*>(Xrow + (size_t)16 * D_)[tid] = f4_to_bf4(mx);
    sm.x *= (1.f/16.f); sm.y *= (1.f/16.f); sm.z *= (1.f/16.f); sm.w *= (1.f/16.f);
    reinterpret_cast<uint2*>(Xrow + (size_t)17 * D_)[tid] = f4_to_bf4(sm);
}

// =====================================================================
// Kernel 2: bf16 tensor GEMM  g_Y[M,256] = X @ W^T
// 64x128x64 block tiles, warp tile 32x32, 3-stage cp.async,
// XOR-swizzled smem, ldmatrix.x4, mma.m16n8k16.bf16.
// grid (72, 2) = 144 blocks = 1 per SM, single wave.
// =====================================================================
#define A_BYTES (64 * 128)          // 8192 B per stage
#define B_BYTES (128 * 128)         // 16384 B per stage
#define STAGE_BYTES (A_BYTES + B_BYTES)  // 24576
#define GEMM_SMEM (3 * STAGE_BYTES)      // 73728

__device__ __forceinline__ void cp_async16(uint32_t dst_s, const uint16_t* src) {
    asm volatile("cp.async.cg.shared.global [%0], [%1], 16;" :: "r"(dst_s), "l"(src));
}

__global__ void __launch_bounds__(256, 1)
gemm_tc_kernel()
{
    extern __shared__ __align__(16) uint16_t smem_b[];
    const uint32_t smem_s = (uint32_t)__cvta_generic_to_shared(smem_b);

    const int tid  = threadIdx.x;
    const int lane = tid & 31;
    const int warp = tid >> 5;
    const int wm   = warp >> 2;     // 0..1  (32 rows each)
    const int wn   = warp & 3;      // 0..3  (32 cols each)
    const int m0   = blockIdx.x * 64;
    const int n0   = blockIdx.y * 128;

    const uint16_t* gA = g_Xb + (size_t)m0 * D_;
    const uint16_t* gB = g_Wb + (size_t)n0 * D_;

    float c[2][4][4];
    #pragma unroll
    for (int i = 0; i < 2; i++)
        #pragma unroll
        for (int j = 0; j < 4; j++)
            #pragma unroll
            for (int r = 0; r < 4; r++) c[i][j][r] = 0.f;

    // loader: per stage, A = 512 chunks of 16B, B = 1024 chunks; 6 per thread.
    #define ISSUE(kt, stg) { \
        uint32_t base = smem_s + (stg) * STAGE_BYTES; \
        _Pragma("unroll") \
        for (int i = 0; i < 6; i++) { \
            int cm, row, ch; uint32_t dst; const uint16_t* src; \
            if (i < 2) { \
                cm = tid + i * 256; row = cm >> 3; ch = cm & 7; \
                dst = base + row * 128 + ((ch ^ (row & 7)) << 4); \
                src = gA + (size_t)row * D_ + (kt) * 64 + ch * 8; \
            } else { \
                cm = tid + (i - 2) * 256; row = cm >> 3; ch = cm & 7; \
                dst = base + A_BYTES + row * 128 + ((ch ^ (row & 7)) << 4); \
                src = gB + (size_t)row * D_ + (kt) * 64 + ch * 8; \
            } \
            cp_async16(dst, src); \
        } \
    }

    ISSUE(0, 0);
    asm volatile("cp.async.commit_group;");
    ISSUE(1, 1);
    asm volatile("cp.async.commit_group;");

    // per-lane ldmatrix geometry
    const int j4   = lane >> 3;          // matrix index 0..3
    const int lr   = lane & 7;           // row within 8x8
    const int aRow = wm * 32 + (j4 & 1) * 8 + lr;
    const int aKj  = j4 >> 1;
    const int aSw  = aRow & 7;
    const int bRow = wn * 32 + (j4 >> 1) * 8 + lr;
    const int bKj  = j4 & 1;
    const int bSw  = bRow & 7;           // (bRow+16)&7 == bSw
    const uint32_t aByte0 = aRow * 128;
    const uint32_t aByte1 = (aRow + 16) * 128;
    const uint32_t bByte0 = bRow * 128;
    const uint32_t bByte1 = (bRow + 16) * 128;

    for (int kt = 0; kt < 16; kt++) {
        asm volatile("cp.async.wait_group 1;");
        __syncthreads();

        const uint32_t As = smem_s + (kt % 3) * STAGE_BYTES;
        const uint32_t Bs = As + A_BYTES;

        #pragma unroll
        for (int step = 0; step < 4; step++) {
            const int cA = (2 * step + aKj) ^ aSw;
            const int cB = (2 * step + bKj) ^ bSw;
            uint32_t a0[4], a1[4], b0[4], b1[4];
            {
                uint32_t addr = As + aByte0 + (cA << 4);
                asm volatile("ldmatrix.sync.aligned.m8n8.x4.shared.b16 {%0,%1,%2,%3}, [%4];"
                             : "=r"(a0[0]), "=r"(a0[1]), "=r"(a0[2]), "=r"(a0[3]) : "r"(addr));
            }
            {
                uint32_t addr = As + aByte1 + (cA << 4);
                asm volatile("ldmatrix.sync.aligned.m8n8.x4.shared.b16 {%0,%1,%2,%3}, [%4];"
                             : "=r"(a1[0]), "=r"(a1[1]), "=r"(a1[2]), "=r"(a1[3]) : "r"(addr));
            }
            {
                uint32_t addr = Bs + bByte0 + (cB << 4);
                asm volatile("ldmatrix.sync.aligned.m8n8.x4.shared.b16 {%0,%1,%2,%3}, [%4];"
                             : "=r"(b0[0]), "=r"(b0[1]), "=r"(b0[2]), "=r"(b0[3]) : "r"(addr));
            }
            {
                uint32_t addr = Bs + bByte1 + (cB << 4);
                asm volatile("ldmatrix.sync.aligned.m8n8.x4.shared.b16 {%0,%1,%2,%3}, [%4];"
                             : "=r"(b1[0]), "=r"(b1[1]), "=r"(b1[2]), "=r"(b1[3]) : "r"(addr));
            }
            #pragma unroll
            for (int mt = 0; mt < 2; mt++) {
                const uint32_t* a = mt ? a1 : a0;
                #pragma unroll
                for (int nt = 0; nt < 4; nt++) {
                    const uint32_t* bb = (nt < 2) ? &b0[(nt & 1) * 2] : &b1[(nt & 1) * 2];
                    asm volatile(
                        "mma.sync.aligned.m16n8k16.row.col.f32.bf16.bf16.f32 "
                        "{%0,%1,%2,%3}, {%4,%5,%6,%7}, {%8,%9}, {%0,%1,%2,%3};"
                        : "+f"(c[mt][nt][0]), "+f"(c[mt][nt][1]),
                          "+f"(c[mt][nt][2]), "+f"(c[mt][nt][3])
                        : "r"(a[0]), "r"(a[1]), "r"(a[2]), "r"(a[3]),
                          "r"(bb[0]), "r"(bb[1]));
                }
            }
        }

        if (kt + 2 < 16) { ISSUE(kt + 2, (kt + 2) % 3); }
        asm volatile("cp.async.commit_group;");
    }

    // epilogue
    const int g  = lane >> 2;
    const int tg = lane & 3;
    #pragma unroll
    for (int mt = 0; mt < 2; mt++) {
        const int rA = m0 + wm * 32 + mt * 16 + g;
        #pragma unroll
        for (int nt = 0; nt < 4; nt++) {
            const int col = n0 + wn * 32 + nt * 8 + 2 * tg;
            *reinterpret_cast<float2*>(g_Y + (size_t)rA * NTOT + col) =
                make_float2(c[mt][nt][0], c[mt][nt][1]);
            *reinterpret_cast<float2*>(g_Y + (size_t)(rA + 8) * NTOT + col) =
                make_float2(c[mt][nt][2], c[mt][nt][3]);
        }
    }
}

// =====================================================================
// Kernel 3: per-b heads. grid = B blocks, 256 threads.
// =====================================================================
__device__ __forceinline__ float gelu_f(float x) {
    return 0.5f * x * (1.0f + erff(x * 0.70710678118654752440f));
}

__global__ void __launch_bounds__(256)
head_kernel(const float* __restrict__ q_b, const float* __restrict__ k_b,
            const float* __restrict__ v_b, const float* __restrict__ mi_b,
            const float* __restrict__ inter_w, const float* __restrict__ inter_b,
            const float* __restrict__ fc0_w, const float* __restrict__ fc0_b,
            const float* __restrict__ fc1_w, const float* __restrict__ fc1_b,
            float* __restrict__ out)
{
    __shared__ float q0[1024], k0[1024], v0[1024];
    __shared__ float q1[1024], k1[1024], v1[1024];
    __shared__ float att[512];
    __shared__ float e1s[1024], e2s[1024];
    __shared__ float sv[4][64];
    __shared__ float aV[256];
    __shared__ float feat[516];
    __shared__ float h1[64];

    int b = blockIdx.x;
    int tid = threadIdx.x;
    const float* Y0 = g_Y + (size_t)(b * 2 + 0) * NROWS * NTOT;
    const float* Y1 = g_Y + (size_t)(b * 2 + 1) * NROWS * NTOT;

    for (int t = tid; t < 1024; t += 256) {
        int n = t >> 6, h = t & 63;
        q0[t] = Y0[n * NTOT +       h] + q_b[h];
        k0[t] = Y0[n * NTOT +  64 + h] + k_b[h];
        v0[t] = Y0[n * NTOT + 128 + h] + v_b[h];
        q1[t] = Y1[n * NTOT +       h] + q_b[h];
        k1[t] = Y1[n * NTOT +  64 + h] + k_b[h];
        v1[t] = Y1[n * NTOT + 128 + h] + v_b[h];
    }
    if (tid < 64) {
        int h = tid;
        sv[0][h] = Y0[16 * NTOT + 192 + h] + mi_b[h];
        sv[1][h] = Y0[17 * NTOT + 192 + h] + mi_b[h];
        sv[2][h] = Y1[16 * NTOT + 192 + h] + mi_b[h];
        sv[3][h] = Y1[17 * NTOT + 192 + h] + mi_b[h];
    }
    __syncthreads();

    for (int e = tid; e < 512; e += 256) {
        int which = e >> 8, n = (e >> 4) & 15, m = e & 15;
        const float* qq = which ? q1 : q0;
        const float* kk = which ? k0 : k1;
        float s = 0.f;
        #pragma unroll
        for (int h = 0; h < 64; h++) s += qq[n * 64 + h] * kk[m * 64 + h];
        att[e] = s * 0.125f;
    }
    __syncthreads();

    for (int e = tid; e < 2048; e += 256) {
        int which = e >> 10, n = (e >> 6) & 15, h = e & 63;
        const float* vv = which ? v0 : v1;
        float s = 0.f;
        #pragma unroll
        for (int m = 0; m < 16; m++) s += att[which * 256 + n * 16 + m] * vv[m * 64 + h];
        (which ? e2s : e1s)[n * 64 + h] = s;
    }
    __syncthreads();

    if (tid < 128) {
        int which = tid >> 6, hh = tid & 63;
        const float* E = which ? e2s : e1s;
        float mx = -3.4e38f, sm = 0.f;
        #pragma unroll
        for (int n = 0; n < 16; n++) { float v = E[n * 64 + hh]; mx = fmaxf(mx, v); sm += v; }
        feat[which * 128 + hh]      = mx;
        feat[which * 128 + 64 + hh] = sm * (1.f / 16.f);
    }

    {
        int i = tid >> 6, j = tid & 63;
        const float* src = sv[i >> 1];
        float s = inter_b[i * 64 + j];
        const float* wrow = inter_w + ((size_t)i * 64 + j) * 64;
        #pragma unroll
        for (int h = 0; h < 64; h++) s += wrow[h] * src[h];
        aV[i * 64 + j] = s;
    }
    __syncthreads();

    if (tid < 4) {
        int i = tid;
        const float* av = aV + i * 64;
        const float* bvv = sv[2 + (i & 1)];
        float dot = 0.f, na = 0.f, nb = 0.f;
        #pragma unroll
        for (int h = 0; h < 64; h++) {
            dot += av[h] * bvv[h];
            na  += av[h] * av[h];
            nb  += bvv[h] * bvv[h];
        }
        na = fmaxf(sqrtf(na), 1e-8f);
        nb = fmaxf(sqrtf(nb), 1e-8f);
        feat[256 + i] = dot / (na * nb);
    }
    feat[260 + tid] = sv[tid >> 6][tid & 63];
    __syncthreads();

    {
        int j = tid >> 2, part = tid & 3;
        const float* wrow = fc0_w + (size_t)j * 516 + part * 129;
        const float* fr = feat + part * 129;
        float s = 0.f;
        #pragma unroll 4
        for (int i = 0; i < 129; i++) s += fr[i] * wrow[i];
        s += __shfl_xor_sync(0xffffffff, s, 1);
        s += __shfl_xor_sync(0xffffffff, s, 2);
        if (part == 0) h1[j] = gelu_f(fc0_b[j] + s);
    }
    __syncthreads();

    if (tid == 0) {
        float l0 = fc1_b[0], l1 = fc1_b[1];
        #pragma unroll
        for (int j = 0; j < 64; j++) { l0 += h1[j] * fc1_w[j]; l1 += h1[j] * fc1_w[64 + j]; }
        l0 = gelu_f(l0); l1 = gelu_f(l1);
        float m = fmaxf(l0, l1);
        float ea = expf(l0 - m), eb = expf(l1 - m);
        float inv = 1.f / (ea + eb);
        out[b * 2 + 0] = ea * inv;
        out[b * 2 + 1] = eb * inv;
    }
}

// =====================================================================
extern "C" void kernel_launch(void* const* d_in, const int* in_sizes, int n_in,
                              void* d_out, int out_size)
{
    const float* token   = (const float*)d_in[0];
    const int*   kw_idx  = (const int*)  d_in[1];
    const float* q_w     = (const float*)d_in[2];
    const float* q_b     = (const float*)d_in[3];
    const float* k_w     = (const float*)d_in[4];
    const float* k_b     = (const float*)d_in[5];
    const float* v_w     = (const float*)d_in[6];
    const float* v_b     = (const float*)d_in[7];
    const float* mi_w    = (const float*)d_in[8];
    const float* mi_b    = (const float*)d_in[9];
    const float* inter_w = (const float*)d_in[10];
    const float* inter_b = (const float*)d_in[11];
    const float* fc0_w   = (const float*)d_in[12];
    const float* fc0_b   = (const float*)d_in[13];
    const float* fc1_w   = (const float*)d_in[14];
    const float* fc1_b   = (const float*)d_in[15];
    float* out = (float*)d_out;

    cudaFuncSetAttribute(gemm_tc_kernel,
                         cudaFuncAttributeMaxDynamicSharedMemorySize, GEMM_SMEM);

    gather_pack_kernel<<<256 + 64, 256>>>(token, kw_idx, q_w, k_w, v_w, mi_w);
    gemm_tc_kernel<<<dim3(MTOT / 64, 2), 256, GEMM_SMEM>>>();
    head_kernel<<<B_, 256>>>(q_b, k_b, v_b, mi_b, inter_w, inter_b,
                             fc0_w, fc0_b, fc1_w, fc1_b, out);
}